// round 5
// baseline (speedup 1.0000x reference)
#include <cuda_runtime.h>
#include <cuda_fp8.h>
#include <cstdint>

// ============================================================================
// y[b,s,o] = 4 * sum_i e4m3(x[b,s,i]*0.5) * W_e4m3[o,i]  + bias[o]
// M = 16384, N = 4096, K = 4096, fp32 out.
// R5: warp-specialized producer/consumer pipeline (Ampere-style mbarriers).
//   CTA 128x128, BK=128, 3 stages. 8 consumer warps (32x64 tile) + 2 producer
//   warps. 2 CTAs/SM. Consumer stream = LDSM + QMMA only.
// ============================================================================

#define DI __device__ __forceinline__

// ---------------- device scratch --------------------------------------------
__device__ uint8_t g_Aq[16384u * 4096u];   // 64MB quantized activations (e4m3)
__device__ uint8_t g_Wq[4096u * 4096u];    // 16MB weight as e4m3 bytes
__device__ int     g_wflag;                // 1 if weight buffer is fp32

// ---------------- helpers ---------------------------------------------------
DI uint32_t smem_u32(const void* p) {
    uint32_t a;
    asm("{ .reg .u64 t; cvta.to.shared.u64 t, %1; cvt.u32.u64 %0, t; }"
        : "=r"(a) : "l"(p));
    return a;
}
DI void cp_async16(uint32_t dst, const void* src) {
    asm volatile("cp.async.cg.shared.global [%0], [%1], 16;" :: "r"(dst), "l"(src));
}
DI void cp_async_mbar_arrive_noinc(uint32_t mbar) {
    asm volatile("cp.async.mbarrier.arrive.noinc.shared.b64 [%0];"
                 :: "r"(mbar) : "memory");
}
DI void ldmatrix4(uint32_t& r0, uint32_t& r1, uint32_t& r2, uint32_t& r3, uint32_t a) {
    asm volatile("ldmatrix.sync.aligned.m8n8.x4.shared.b16 {%0,%1,%2,%3}, [%4];"
                 : "=r"(r0), "=r"(r1), "=r"(r2), "=r"(r3) : "r"(a));
}
DI void mma_e4m3(float& c0, float& c1, float& c2, float& c3,
                 uint32_t a0, uint32_t a1, uint32_t a2, uint32_t a3,
                 uint32_t b0, uint32_t b1) {
    asm volatile(
        "mma.sync.aligned.m16n8k32.row.col.f32.e4m3.e4m3.f32 "
        "{%0,%1,%2,%3}, {%4,%5,%6,%7}, {%8,%9}, {%0,%1,%2,%3};"
        : "+f"(c0), "+f"(c1), "+f"(c2), "+f"(c3)
        : "r"(a0), "r"(a1), "r"(a2), "r"(a3), "r"(b0), "r"(b1));
}

#define MBARRIER_INIT(addr, count) \
    asm volatile("mbarrier.init.shared.b64 [%0], %1;" \
                 :: "r"((uint32_t)(addr)), "r"((uint32_t)(count)) : "memory")
#define MBARRIER_ARRIVE(addr) \
    asm volatile("mbarrier.arrive.shared.b64 _, [%0];" \
                 :: "r"((uint32_t)(addr)) : "memory")
#define MBARRIER_WAIT_PARITY(mbar_smem_addr, phase_parity) do { \
    uint32_t _mbar = (uint32_t)(mbar_smem_addr); \
    uint32_t _parity = (uint32_t)(phase_parity); \
    uint32_t _done; \
    asm volatile( \
        "{\n\t" \
        ".reg .pred p;\n\t" \
        "mbarrier.try_wait.parity.acquire.cta.shared::cta.b64 p, [%1], %2;\n\t" \
        "selp.b32 %0, 1, 0, p;\n\t" \
        "}" \
        : "=r"(_done) : "r"(_mbar), "r"(_parity) : "memory"); \
    if (!_done) { \
        asm volatile( \
            "{\n\t" \
            ".reg .pred P1;\n\t" \
            "WAIT_LOOP_%=:\n\t" \
            "mbarrier.try_wait.parity.acquire.cta.shared::cta.b64 P1, [%0], %1, 0x989680;\n\t" \
            "@P1 bra.uni WAIT_DONE_%=;\n\t" \
            "bra.uni WAIT_LOOP_%=;\n\t" \
            "WAIT_DONE_%=:\n\t" \
            "}" \
            :: "r"(_mbar), "r"(_parity) : "memory"); \
    } \
} while(0)

// ============================================================================
// Kernel 1: quantize activations  e4m3(x * 0.5)
// ============================================================================
__global__ void quant_act(const float4* __restrict__ in, int n4) {
    uint32_t* out = reinterpret_cast<uint32_t*>(g_Aq);
    int i = blockIdx.x * blockDim.x + threadIdx.x;
    int stride = gridDim.x * blockDim.x;
    for (; i < n4; i += stride) {
        float4 v = in[i];
        __nv_fp8x2_storage_t p0 = __nv_cvt_float2_to_fp8x2(
            make_float2(v.x * 0.5f, v.y * 0.5f), __NV_SATFINITE, __NV_E4M3);
        __nv_fp8x2_storage_t p1 = __nv_cvt_float2_to_fp8x2(
            make_float2(v.z * 0.5f, v.w * 0.5f), __NV_SATFINITE, __NV_E4M3);
        out[i] = (uint32_t)p0 | ((uint32_t)p1 << 16);
    }
}

// ============================================================================
// Kernel 2: weight dtype detect + normalize to e4m3 bytes
// ============================================================================
__global__ void detect_wdtype(const float* __restrict__ w) {
    if (blockIdx.x == 0 && threadIdx.x == 0) {
        int ok = 1;
        for (int i = 0; i < 256; i++) {
            float x = w[i];
            if (!(fabsf(x) <= 448.0f)) { ok = 0; break; }
        }
        g_wflag = ok;
    }
}

__global__ void prep_w(const void* __restrict__ w, int n) {
    int flag = g_wflag;
    int idx = blockIdx.x * blockDim.x + threadIdx.x;
    int stride = gridDim.x * blockDim.x;
    if (flag) {
        const float4* wf = (const float4*)w;
        uint32_t* o = reinterpret_cast<uint32_t*>(g_Wq);
        for (int i = idx; i < n / 4; i += stride) {
            float4 v = wf[i];
            __nv_fp8x2_storage_t p0 = __nv_cvt_float2_to_fp8x2(
                make_float2(v.x, v.y), __NV_SATFINITE, __NV_E4M3);
            __nv_fp8x2_storage_t p1 = __nv_cvt_float2_to_fp8x2(
                make_float2(v.z, v.w), __NV_SATFINITE, __NV_E4M3);
            o[i] = (uint32_t)p0 | ((uint32_t)p1 << 16);
        }
    } else {
        const uint4* wb = (const uint4*)w;
        uint4* o = reinterpret_cast<uint4*>(g_Wq);
        for (int i = idx; i < n / 16; i += stride) o[i] = wb[i];
    }
}

// ============================================================================
// Kernel 3: warp-specialized FP8 GEMM
// ============================================================================
#define BM 128
#define BN 128
#define BK 128
#define KDIM 4096
#define NDIM 4096
#define MDIM 16384
#define KCHUNKS (KDIM / BK)          // 32
#define STAGES 3
#define NTHREADS 320                 // 256 consumer + 64 producer

#define A_BYTES (BM * BK)            // 16384
#define B_BYTES (BN * BK)            // 16384
#define STAGE_BYTES (A_BYTES + B_BYTES)   // 32768
#define SM_DATA 1024                 // data after mbarriers
#define SM_TOTAL (SM_DATA + STAGES * STAGE_BYTES)   // 99328

// mbarriers: full[s] at s*16, empty[s] at s*16+8
__global__ void __launch_bounds__(NTHREADS, 2)
gemm_kernel(const float* __restrict__ bias, float* __restrict__ out) {
    extern __shared__ char smem[];
    uint32_t sb = smem_u32(smem);
    uint32_t mb = sb;
    uint32_t data = sb + SM_DATA;
    int tid = (int)threadIdx.x;
    int tm = blockIdx.y;
    int tn = blockIdx.x;

    if (tid == 0) {
#pragma unroll
        for (int s = 0; s < STAGES; s++) {
            MBARRIER_INIT(mb + s * 16, 64);      // full: 64 producer threads
            MBARRIER_INIT(mb + s * 16 + 8, 8);   // empty: 8 consumer warps
        }
    }
    __syncthreads();

    if (tid >= 256) {
        // ---------------- producer: 2 warps, 64 threads ----------------
        int ptid = tid - 256;
        int col = ptid & 7;           // 16B unit within 128B row
        int row0 = ptid >> 3;         // 0..7
        // swizzled unit is constant per thread: rows stride by 8
        uint32_t aSm0 = (uint32_t)(row0 * 128 + ((col ^ row0) << 4));
        uint32_t bSm0 = aSm0 + A_BYTES;
        const uint8_t* ag = g_Aq + ((size_t)(tm * BM + row0)) * KDIM + col * 16;
        const uint8_t* bg = g_Wq + ((size_t)(tn * BN + row0)) * KDIM + col * 16;

        int stage = 0, phase = 1;
        for (int ck = 0; ck < KCHUNKS; ck++) {
            MBARRIER_WAIT_PARITY(mb + stage * 16 + 8, phase);
            uint32_t As = data + stage * STAGE_BYTES + aSm0;
            uint32_t Bs = data + stage * STAGE_BYTES + bSm0;
#pragma unroll
            for (int i = 0; i < 16; i++)
                cp_async16(As + i * 1024, ag + (size_t)i * (8 * KDIM));
#pragma unroll
            for (int i = 0; i < 16; i++)
                cp_async16(Bs + i * 1024, bg + (size_t)i * (8 * KDIM));
            cp_async_mbar_arrive_noinc(mb + stage * 16);
            ag += BK;
            bg += BK;
            if (++stage == STAGES) { stage = 0; phase ^= 1; }
        }
        return;
    }

    // ---------------- consumer: 8 warps, warp tile 32(M) x 64(N) ------------
    int wid = tid >> 5;
    int lid = tid & 31;
    int wm = wid & 3;                 // 4 warps * 32 rows
    int wn = wid >> 2;                // 2 warps * 64 cols

    float acc[2][8][4];
#pragma unroll
    for (int mi = 0; mi < 2; mi++)
#pragma unroll
        for (int ni = 0; ni < 8; ni++)
#pragma unroll
            for (int r = 0; r < 4; r++) acc[mi][ni][r] = 0.0f;

    // lane-derived ldmatrix coordinates (proven R2-R4)
    int a_row_l = (lid & 7) + ((lid >> 3) & 1) * 8;
    int a_half  = lid >> 4;
    int b_row_l = (lid & 7) + ((lid >> 4) & 1) * 8;
    int b_half  = (lid >> 3) & 1;

    uint32_t aOff[2], bOff[4];
#pragma unroll
    for (int mi = 0; mi < 2; mi++) {
        int row = wm * 32 + mi * 16 + a_row_l;
        aOff[mi] = (uint32_t)(row * 128 + ((a_half ^ (row & 7)) << 4));
    }
#pragma unroll
    for (int np = 0; np < 4; np++) {
        int n = wn * 64 + np * 16 + b_row_l;
        bOff[np] = (uint32_t)(n * 128 + ((b_half ^ (n & 7)) << 4)) + A_BYTES;
    }

    int stage = 0, phase = 0;
    for (int ck = 0; ck < KCHUNKS; ck++) {
        MBARRIER_WAIT_PARITY(mb + stage * 16, phase);
        uint32_t S = data + stage * STAGE_BYTES;
#pragma unroll
        for (int ks = 0; ks < 4; ks++) {
            uint32_t x = (uint32_t)(ks << 5);
            uint32_t a[2][4];
            uint32_t b[8][2];
#pragma unroll
            for (int mi = 0; mi < 2; mi++)
                ldmatrix4(a[mi][0], a[mi][1], a[mi][2], a[mi][3],
                          (S + aOff[mi]) ^ x);
#pragma unroll
            for (int np = 0; np < 4; np++)
                ldmatrix4(b[2 * np][0], b[2 * np][1],
                          b[2 * np + 1][0], b[2 * np + 1][1],
                          (S + bOff[np]) ^ x);
#pragma unroll
            for (int mi = 0; mi < 2; mi++)
#pragma unroll
                for (int ni = 0; ni < 8; ni++)
                    mma_e4m3(acc[mi][ni][0], acc[mi][ni][1],
                             acc[mi][ni][2], acc[mi][ni][3],
                             a[mi][0], a[mi][1], a[mi][2], a[mi][3],
                             b[ni][0], b[ni][1]);
        }
        if (lid == 0) MBARRIER_ARRIVE(mb + stage * 16 + 8);
        if (++stage == STAGES) { stage = 0; phase ^= 1; }
    }

    // Epilogue: out = acc*4 + bias
    int qrow = lid >> 2;
    int qcol = (lid & 3) * 2;
    int m0 = tm * BM + wm * 32 + qrow;
    int n0 = tn * BN + wn * 64 + qcol;
#pragma unroll
    for (int mi = 0; mi < 2; mi++) {
#pragma unroll
        for (int ni = 0; ni < 8; ni++) {
            int n = n0 + ni * 8;
            float b0 = __ldg(bias + n);
            float b1 = __ldg(bias + n + 1);
            int mA = m0 + mi * 16;
            int mB = mA + 8;
            float2 v0 = make_float2(acc[mi][ni][0] * 4.0f + b0,
                                    acc[mi][ni][1] * 4.0f + b1);
            float2 v1 = make_float2(acc[mi][ni][2] * 4.0f + b0,
                                    acc[mi][ni][3] * 4.0f + b1);
            *reinterpret_cast<float2*>(out + (size_t)mA * NDIM + n) = v0;
            *reinterpret_cast<float2*>(out + (size_t)mB * NDIM + n) = v1;
        }
    }
}

// ============================================================================
// Host launch
// ============================================================================
extern "C" void kernel_launch(void* const* d_in, const int* in_sizes, int n_in,
                              void* d_out, int out_size) {
    const float* input = nullptr;
    const void*  weight = nullptr;
    const float* bias = nullptr;
    for (int i = 0; i < n_in; i++) {
        if (in_sizes[i] == 4 * 4096 * 4096)  input = (const float*)d_in[i];
        else if (in_sizes[i] == 4096 * 4096) weight = d_in[i];
        else if (in_sizes[i] == 4096)        bias = (const float*)d_in[i];
    }
    if (!input)  input  = (const float*)d_in[0];
    if (!weight) weight = d_in[1];
    if (!bias)   bias   = (const float*)d_in[2];
    float* out = (float*)d_out;

    int n4 = (4 * 4096 * 4096) / 4;
    quant_act<<<8192, 256>>>((const float4*)input, n4);

    detect_wdtype<<<1, 1>>>((const float*)weight);
    prep_w<<<2048, 256>>>(weight, 4096 * 4096);

    static bool attr_set = false;
    if (!attr_set) {
        cudaFuncSetAttribute(gemm_kernel,
                             cudaFuncAttributeMaxDynamicSharedMemorySize, SM_TOTAL);
        attr_set = true;
    }
    dim3 grid(NDIM / BN, MDIM / BM);   // (32, 128)
    gemm_kernel<<<grid, NTHREADS, SM_TOTAL>>>(bias, out);
}

// round 6
// speedup vs baseline: 1.6487x; 1.6487x over previous
#include <cuda_runtime.h>
#include <cuda_fp8.h>
#include <cstdint>

// ============================================================================
// y[b,s,o] = 4 * sum_i e4m3(x[b,s,i]*0.5) * W_e4m3[o,i]  + bias[o]
// M = 16384, N = 4096, K = 4096, fp32 out.
// R6: R4 structure (best) + strength-reduced addressing:
//   CTA 128x128, 256 thr, 2 CTAs/SM, BK=128, 3 stages, frag double-buffer,
//   per-thread constant swizzle bases, pointer-increment global addressing.
// ============================================================================

#define DI __device__ __forceinline__

// ---------------- device scratch --------------------------------------------
__device__ uint8_t g_Aq[16384u * 4096u];   // 64MB quantized activations (e4m3)
__device__ uint8_t g_Wq[4096u * 4096u];    // 16MB weight as e4m3 bytes
__device__ int     g_wflag;                // 1 if weight buffer is fp32

// ---------------- helpers ---------------------------------------------------
DI uint32_t smem_u32(const void* p) {
    uint32_t a;
    asm("{ .reg .u64 t; cvta.to.shared.u64 t, %1; cvt.u32.u64 %0, t; }"
        : "=r"(a) : "l"(p));
    return a;
}
DI void cp_async16(uint32_t dst, const void* src) {
    asm volatile("cp.async.cg.shared.global [%0], [%1], 16;" :: "r"(dst), "l"(src));
}
DI void cp_commit() { asm volatile("cp.async.commit_group;" ::: "memory"); }
template <int N> DI void cp_wait() {
    asm volatile("cp.async.wait_group %0;" :: "n"(N) : "memory");
}
DI void ldmatrix4(uint32_t& r0, uint32_t& r1, uint32_t& r2, uint32_t& r3, uint32_t a) {
    asm volatile("ldmatrix.sync.aligned.m8n8.x4.shared.b16 {%0,%1,%2,%3}, [%4];"
                 : "=r"(r0), "=r"(r1), "=r"(r2), "=r"(r3) : "r"(a));
}
DI void mma_e4m3(float& c0, float& c1, float& c2, float& c3,
                 uint32_t a0, uint32_t a1, uint32_t a2, uint32_t a3,
                 uint32_t b0, uint32_t b1) {
    asm volatile(
        "mma.sync.aligned.m16n8k32.row.col.f32.e4m3.e4m3.f32 "
        "{%0,%1,%2,%3}, {%4,%5,%6,%7}, {%8,%9}, {%0,%1,%2,%3};"
        : "+f"(c0), "+f"(c1), "+f"(c2), "+f"(c3)
        : "r"(a0), "r"(a1), "r"(a2), "r"(a3), "r"(b0), "r"(b1));
}

// ============================================================================
// Kernel 1: quantize activations  e4m3(x * 0.5)
// ============================================================================
__global__ void quant_act(const float4* __restrict__ in, int n4) {
    uint32_t* out = reinterpret_cast<uint32_t*>(g_Aq);
    int i = blockIdx.x * blockDim.x + threadIdx.x;
    int stride = gridDim.x * blockDim.x;
    for (; i < n4; i += stride) {
        float4 v = in[i];
        __nv_fp8x2_storage_t p0 = __nv_cvt_float2_to_fp8x2(
            make_float2(v.x * 0.5f, v.y * 0.5f), __NV_SATFINITE, __NV_E4M3);
        __nv_fp8x2_storage_t p1 = __nv_cvt_float2_to_fp8x2(
            make_float2(v.z * 0.5f, v.w * 0.5f), __NV_SATFINITE, __NV_E4M3);
        out[i] = (uint32_t)p0 | ((uint32_t)p1 << 16);
    }
}

// ============================================================================
// Kernel 2: weight dtype detect + normalize to e4m3 bytes
// ============================================================================
__global__ void detect_wdtype(const float* __restrict__ w) {
    if (blockIdx.x == 0 && threadIdx.x == 0) {
        int ok = 1;
        for (int i = 0; i < 256; i++) {
            float x = w[i];
            if (!(fabsf(x) <= 448.0f)) { ok = 0; break; }
        }
        g_wflag = ok;
    }
}

__global__ void prep_w(const void* __restrict__ w, int n) {
    int flag = g_wflag;
    int idx = blockIdx.x * blockDim.x + threadIdx.x;
    int stride = gridDim.x * blockDim.x;
    if (flag) {
        const float4* wf = (const float4*)w;
        uint32_t* o = reinterpret_cast<uint32_t*>(g_Wq);
        for (int i = idx; i < n / 4; i += stride) {
            float4 v = wf[i];
            __nv_fp8x2_storage_t p0 = __nv_cvt_float2_to_fp8x2(
                make_float2(v.x, v.y), __NV_SATFINITE, __NV_E4M3);
            __nv_fp8x2_storage_t p1 = __nv_cvt_float2_to_fp8x2(
                make_float2(v.z, v.w), __NV_SATFINITE, __NV_E4M3);
            o[i] = (uint32_t)p0 | ((uint32_t)p1 << 16);
        }
    } else {
        const uint4* wb = (const uint4*)w;
        uint4* o = reinterpret_cast<uint4*>(g_Wq);
        for (int i = idx; i < n / 16; i += stride) o[i] = wb[i];
    }
}

// ============================================================================
// Kernel 3: FP8 GEMM
// ============================================================================
#define BM 128
#define BN 128
#define BK 128
#define KDIM 4096
#define NDIM 4096
#define MDIM 16384
#define KCHUNKS (KDIM / BK)          // 32
#define STAGES 3
#define NTHREADS 256

#define A_BYTES (BM * BK)            // 16384
#define B_BYTES (BN * BK)            // 16384
#define STAGE_BYTES (A_BYTES + B_BYTES)   // 32768
#define SM_TOTAL (STAGES * STAGE_BYTES)   // 98304 per CTA

// All 256 threads: thread loads 4 A rows + 4 B rows (rows stride 32, so the
// swizzled 16B unit (col ^ (row&7)) is a per-thread CONSTANT).
DI void load_stage(uint32_t As, uint32_t Bs,
                   const uint8_t* __restrict__ ag,
                   const uint8_t* __restrict__ bg) {
#pragma unroll
    for (int i = 0; i < BM / 32; i++)
        cp_async16(As + i * (32 * 128), ag + (size_t)i * (32 * KDIM));
#pragma unroll
    for (int i = 0; i < BN / 32; i++)
        cp_async16(Bs + i * (32 * 128), bg + (size_t)i * (32 * KDIM));
}

__global__ void __launch_bounds__(NTHREADS, 2)
gemm_kernel(const float* __restrict__ bias, float* __restrict__ out) {
    extern __shared__ char smem[];
    uint32_t sb = smem_u32(smem);
    int tid = (int)threadIdx.x;
    int wid = tid >> 5;
    int lid = tid & 31;
    int wm = wid & 1;                 // M dir: 2 warps * 64 rows
    int wn = wid >> 1;                // N dir: 4 warps * 32 cols
    int tm = blockIdx.y;
    int tn = blockIdx.x;

    // ---- per-thread constant load addressing ----
    int lcol = tid & 7;               // 16B unit within 128B row
    int lrow = tid >> 3;              // 0..31
    uint32_t aSmBase = (uint32_t)(lrow * 128 + ((lcol ^ (lrow & 7)) << 4));
    uint32_t bSmBase = aSmBase + A_BYTES;
    const uint8_t* ag = g_Aq + ((size_t)(tm * BM + lrow)) * KDIM + lcol * 16;
    const uint8_t* bg = g_Wq + ((size_t)(tn * BN + lrow)) * KDIM + lcol * 16;

    float acc[4][4][4];
#pragma unroll
    for (int mi = 0; mi < 4; mi++)
#pragma unroll
        for (int ni = 0; ni < 4; ni++)
#pragma unroll
            for (int r = 0; r < 4; r++) acc[mi][ni][r] = 0.0f;

    // lane-derived ldmatrix source coordinates (proven R2-R4)
    int a_row_l = (lid & 7) + ((lid >> 3) & 1) * 8;
    int a_half  = lid >> 4;
    int b_row_l = (lid & 7) + ((lid >> 4) & 1) * 8;
    int b_half  = (lid >> 3) & 1;

    uint32_t aOff[4], bOff[2];
#pragma unroll
    for (int mi = 0; mi < 4; mi++) {
        int row = wm * 64 + mi * 16 + a_row_l;
        aOff[mi] = (uint32_t)(row * 128 + ((a_half ^ (row & 7)) << 4));
    }
#pragma unroll
    for (int np = 0; np < 2; np++) {
        int n = wn * 32 + np * 16 + b_row_l;
        bOff[np] = (uint32_t)(n * 128 + ((b_half ^ (n & 7)) << 4)) + A_BYTES;
    }

    // prologue: fill stages 0,1; advance global pointers by BK each
#pragma unroll
    for (int s = 0; s < STAGES - 1; s++) {
        load_stage(sb + s * STAGE_BYTES + aSmBase, sb + s * STAGE_BYTES + bSmBase,
                   ag, bg);
        cp_commit();
        ag += BK;
        bg += BK;
    }

    uint32_t a[2][4][4];
    uint32_t b[2][4][2];
    int cs = 0;                        // compute stage
    int ps = STAGES - 1;               // produce stage

    for (int ck = 0; ck < KCHUNKS; ck++) {
        cp_wait<STAGES - 2>();
        __syncthreads();
        if (ck + STAGES - 1 < KCHUNKS) {
            load_stage(sb + ps * STAGE_BYTES + aSmBase,
                       sb + ps * STAGE_BYTES + bSmBase, ag, bg);
            ag += BK;
            bg += BK;
            if (++ps == STAGES) ps = 0;
        }
        cp_commit();                  // uniform group accounting

        uint32_t As = sb + cs * STAGE_BYTES;
        uint32_t Bs = As;             // bOff already includes +A_BYTES
        if (++cs == STAGES) cs = 0;

        uint32_t aB[4], bB[2];
#pragma unroll
        for (int mi = 0; mi < 4; mi++) aB[mi] = As + aOff[mi];
#pragma unroll
        for (int np = 0; np < 2; np++) bB[np] = Bs + bOff[np];

        // preload ks = 0 fragments
#pragma unroll
        for (int mi = 0; mi < 4; mi++)
            ldmatrix4(a[0][mi][0], a[0][mi][1], a[0][mi][2], a[0][mi][3], aB[mi]);
#pragma unroll
        for (int np = 0; np < 2; np++)
            ldmatrix4(b[0][2 * np][0], b[0][2 * np][1],
                      b[0][2 * np + 1][0], b[0][2 * np + 1][1], bB[np]);

#pragma unroll
        for (int ks = 0; ks < 4; ks++) {
            int cur = ks & 1;
            int nxt = cur ^ 1;
            if (ks < 3) {
                uint32_t x = (uint32_t)((ks + 1) << 5);
#pragma unroll
                for (int mi = 0; mi < 4; mi++)
                    ldmatrix4(a[nxt][mi][0], a[nxt][mi][1], a[nxt][mi][2], a[nxt][mi][3],
                              aB[mi] ^ x);
#pragma unroll
                for (int np = 0; np < 2; np++)
                    ldmatrix4(b[nxt][2 * np][0], b[nxt][2 * np][1],
                              b[nxt][2 * np + 1][0], b[nxt][2 * np + 1][1],
                              bB[np] ^ x);
            }
#pragma unroll
            for (int mi = 0; mi < 4; mi++)
#pragma unroll
                for (int ni = 0; ni < 4; ni++)
                    mma_e4m3(acc[mi][ni][0], acc[mi][ni][1], acc[mi][ni][2], acc[mi][ni][3],
                             a[cur][mi][0], a[cur][mi][1], a[cur][mi][2], a[cur][mi][3],
                             b[cur][ni][0], b[cur][ni][1]);
        }
    }

    // Epilogue: out = acc*4 + bias
    int qrow = lid >> 2;
    int qcol = (lid & 3) * 2;
    int m0 = tm * BM + wm * 64 + qrow;
    int n0 = tn * BN + wn * 32 + qcol;
#pragma unroll
    for (int mi = 0; mi < 4; mi++) {
#pragma unroll
        for (int ni = 0; ni < 4; ni++) {
            int n = n0 + ni * 8;
            float b0 = __ldg(bias + n);
            float b1 = __ldg(bias + n + 1);
            int mA = m0 + mi * 16;
            int mB = mA + 8;
            float2 v0 = make_float2(acc[mi][ni][0] * 4.0f + b0,
                                    acc[mi][ni][1] * 4.0f + b1);
            float2 v1 = make_float2(acc[mi][ni][2] * 4.0f + b0,
                                    acc[mi][ni][3] * 4.0f + b1);
            *reinterpret_cast<float2*>(out + (size_t)mA * NDIM + n) = v0;
            *reinterpret_cast<float2*>(out + (size_t)mB * NDIM + n) = v1;
        }
    }
}

// ============================================================================
// Host launch
// ============================================================================
extern "C" void kernel_launch(void* const* d_in, const int* in_sizes, int n_in,
                              void* d_out, int out_size) {
    const float* input = nullptr;
    const void*  weight = nullptr;
    const float* bias = nullptr;
    for (int i = 0; i < n_in; i++) {
        if (in_sizes[i] == 4 * 4096 * 4096)  input = (const float*)d_in[i];
        else if (in_sizes[i] == 4096 * 4096) weight = d_in[i];
        else if (in_sizes[i] == 4096)        bias = (const float*)d_in[i];
    }
    if (!input)  input  = (const float*)d_in[0];
    if (!weight) weight = d_in[1];
    if (!bias)   bias   = (const float*)d_in[2];
    float* out = (float*)d_out;

    int n4 = (4 * 4096 * 4096) / 4;
    quant_act<<<8192, 256>>>((const float4*)input, n4);

    detect_wdtype<<<1, 1>>>((const float*)weight);
    prep_w<<<2048, 256>>>(weight, 4096 * 4096);

    static bool attr_set = false;
    if (!attr_set) {
        cudaFuncSetAttribute(gemm_kernel,
                             cudaFuncAttributeMaxDynamicSharedMemorySize, SM_TOTAL);
        attr_set = true;
    }
    dim3 grid(NDIM / BN, MDIM / BM);   // (32, 128)
    gemm_kernel<<<grid, NTHREADS, SM_TOTAL>>>(bias, out);
}